// round 8
// baseline (speedup 1.0000x reference)
#include <cuda_runtime.h>
#include <math.h>

// ---------------------------------------------------------------------------
// AvULoss: N=2^21 rows, C=32. Persistent threads, 4 threads/row, no smem,
// register double-buffered LDG.128 pipeline, labels pipelined 2 deep,
// quad shfl_xor reduction, tail computed redundantly on all 4 lanes
// (num/den both x4 -> ratio unchanged).
//   y = x*log2e, e = 2^y; S = sum e, dot = sum e*y, emax = max e
//   conf = emax/S ; unc = ln2*(log2 S - dot/S)
//   accurate = (2^(xlab*log2e) == emax)   (xlab via direct scalar LDG, L1 hit)
//   num = sum w*[accurate==certain], den = sum w
//   loss = -log(num/(den+1e-10) + 1e-10)
// Last-block ticket finalizes + resets accumulators (graph-replay safe).
// Labels arrive as int32 (JAX x64-disabled downcasts the int64 randint).
// ---------------------------------------------------------------------------

#define BLOCK 256
#define LOG2E 1.4426950408889634f
#define LN2   0.6931471805599453f

__device__ double g_acc[2];
__device__ unsigned int g_ticket = 0;

__device__ __forceinline__ float tanh_approx(float x) {
    float r;
    asm("tanh.approx.f32 %0, %1;" : "=f"(r) : "f"(x));
    return r;
}

__global__ __launch_bounds__(BLOCK, 5)
void avu_kernel(const float4* __restrict__ logits4,
                const float* __restrict__ logits_s,
                const int* __restrict__ labels,
                const float* __restrict__ unc_th_p,
                float* __restrict__ out,
                int N)
{
    __shared__ float sred[16];               // 8 warps x {num, den}
    __shared__ bool s_last;

    const int tid  = threadIdx.x;
    const int lane = tid & 31;
    const unsigned quad = tid & 3;

    int row = (blockIdx.x * BLOCK + tid) >> 2;      // uniform within quad
    const int rstride = (gridDim.x * BLOCK) >> 2;   // rows per chip-iter
    const float th = __ldg(unc_th_p);

    float num = 0.f, den = 0.f;

    // ---- depth-2 pipelined prologue ----
    // lab:  need labs for iter k+1 loaded at iter k   (depth 2 at steady state)
    // xlab: for iter k+1 loaded at iter k (depends on lab loaded at k-1)
    float4 a, b;                 // logits for current iter
    float xlab_cur;              // x[label] for current iter
    int   lab_next;              // label for next iter
    {
        unsigned r0 = (unsigned)(row < N ? row : N - 1);
        unsigned o0 = r0 * 8u + quad * 2u;
        a = logits4[o0];
        b = logits4[o0 + 1];
        int lab0 = labels[r0];
        xlab_cur = logits_s[r0 * 32u + (unsigned)lab0];

        int r1 = row + rstride;
        unsigned r1c = (unsigned)(r1 < N ? r1 : N - 1);
        lab_next = labels[r1c];
    }

    while (row < N) {                        // warp-uniform (64-row chunks)
        int rnext = row + rstride;

        // ---- prefetch next logits + xlab(next) + lab(next+1) ----
        float4 an, bn; float xlab_n; int lab_nn;
        {
            unsigned rn = (unsigned)(rnext < N ? rnext : N - 1);
            unsigned on = rn * 8u + quad * 2u;
            an = logits4[on];
            bn = logits4[on + 1];
            xlab_n = logits_s[rn * 32u + (unsigned)lab_next];

            int r2 = rnext + rstride;
            unsigned r2c = (unsigned)(r2 < N ? r2 : N - 1);
            lab_nn = labels[r2c];
        }

        // ---- compute current: S, dot, emax over this thread's 8 elems ----
        float xs[8] = {a.x, a.y, a.z, a.w, b.x, b.y, b.z, b.w};
        float S = 0.f, dot = 0.f, emax = 0.f;
#pragma unroll
        for (int j = 0; j < 8; ++j) {
            float y = xs[j] * LOG2E;
            float e = exp2f(y);
            S += e;
            dot = __fmaf_rn(e, y, dot);
            emax = fmaxf(emax, e);
        }

        // ---- quad reduction (all lanes receive the row totals) ----
#pragma unroll
        for (int o = 1; o < 4; o <<= 1) {
            S    += __shfl_xor_sync(0xffffffffu, S,    o);
            dot  += __shfl_xor_sync(0xffffffffu, dot,  o);
            emax  = fmaxf(emax, __shfl_xor_sync(0xffffffffu, emax, o));
        }

        // ---- per-row tail, all 4 lanes (num/den scale x4; ratio invariant) ----
        {
            float invS = __frcp_rn(S);
            float conf = emax * invS;                       // max softmax prob
            float unc  = LN2 * (__log2f(S) - dot * invS);   // predictive entropy
            float elab = exp2f(xlab_cur * LOG2E);
            bool accurate = (elab == emax);
            bool certain  = (unc <= th);
            float t = tanh_approx(unc);
            float w = (accurate ? conf : (1.f - conf)) * (certain ? (1.f - t) : t);
            num += (accurate == certain) ? w : 0.f;         // cats ac + iu
            den += w;
        }

        a = an; b = bn; xlab_cur = xlab_n; lab_next = lab_nn;
        row = rnext;
    }

    // ---- block reduction of (num, den), once ----
#pragma unroll
    for (int o = 16; o > 0; o >>= 1) {
        num += __shfl_down_sync(0xffffffffu, num, o);
        den += __shfl_down_sync(0xffffffffu, den, o);
    }
    const int wid = tid >> 5;
    if (lane == 0) {
        sred[wid]     = num;
        sred[wid + 8] = den;
    }
    __syncthreads();

    if (tid < 2) {
        double s = 0.0;
#pragma unroll
        for (int wv = 0; wv < 8; ++wv) s += (double)sred[tid * 8 + wv];
        atomicAdd(&g_acc[tid], s);
        __threadfence();
    }
    __syncthreads();

    // ---- last-block finalize + reset (graph-replay deterministic) ----
    if (tid == 0) {
        unsigned int ticket = atomicAdd(&g_ticket, 1u);
        s_last = (ticket == gridDim.x - 1u);
    }
    __syncthreads();
    if (s_last && tid == 0) {
        volatile double* acc = g_acc;
        double nsum = acc[0], dsum = acc[1];
        double avu = nsum / (dsum + 1e-10);   // both x4: ratio unchanged
        out[0] = (float)(-log(avu + 1e-10));
        g_acc[0] = 0.0; g_acc[1] = 0.0;
        __threadfence();
        g_ticket = 0u;
    }
}

extern "C" void kernel_launch(void* const* d_in, const int* in_sizes, int n_in,
                              void* d_out, int out_size)
{
    const float4* logits4 = (const float4*)d_in[0];
    const float*  logits_s = (const float*)d_in[0];
    const int*    labels  = (const int*)d_in[1];
    const float*  unc_th  = (const float*)d_in[2];
    float* out = (float*)d_out;

    const int N = in_sizes[1];               // rows (2^21)
    int grid = 148 * 5;                      // matches __launch_bounds__(256,5)
    int maxBlocks = (N + (BLOCK / 4) - 1) / (BLOCK / 4);
    if (grid > maxBlocks) grid = maxBlocks;

    avu_kernel<<<grid, BLOCK>>>(logits4, logits_s, labels, unc_th, out, N);
}